// round 6
// baseline (speedup 1.0000x reference)
#include <cuda_runtime.h>
#include <cstdint>

#define BB 256
#define TT 2048
#define II 64
#define HH 256

// Persistent scratch for the input projection (zero-init; t>=len never written).
__device__ float g_xp[(size_t)BB * TT * HH];
// FC partials: [batch][cta-rank]
__device__ float g_part[BB][2];

typedef unsigned long long u64;

__device__ __forceinline__ u64 pack2(float lo, float hi) {
    u64 r; asm("mov.b64 %0, {%1,%2};" : "=l"(r) : "f"(lo), "f"(hi)); return r;
}
__device__ __forceinline__ void ffma2(u64& acc, u64 a, u64 b) {
    asm("fma.rn.f32x2 %0, %1, %2, %0;" : "+l"(acc) : "l"(a), "l"(b));
}
__device__ __forceinline__ u64 add2(u64 a, u64 b) {
    u64 r; asm("add.rn.f32x2 %0, %1, %2;" : "=l"(r) : "l"(a), "l"(b)); return r;
}
__device__ __forceinline__ float2 unpack2(u64 v) {
    float2 f; asm("mov.b64 {%0,%1}, %2;" : "=f"(f.x), "=f"(f.y) : "l"(v)); return f;
}
__device__ __forceinline__ uint32_t smem_u32(const void* p) {
    uint32_t a;
    asm("{ .reg .u64 t; cvta.to.shared.u64 t, %1; cvt.u32.u64 %0, t; }" : "=r"(a) : "l"(p));
    return a;
}
__device__ __forceinline__ uint32_t mapa_u32(uint32_t laddr, uint32_t rank) {
    uint32_t r;
    asm("mapa.shared::cluster.u32 %0, %1, %2;" : "=r"(r) : "r"(laddr), "r"(rank));
    return r;
}

// ---------------------------------------------------------------------------
// Kernel A: xp[b,t,h] = sum_i x[b,t,i]*W_ih[h,i] + b_ih[h] + b_hh[h], t < len[b]
// ---------------------------------------------------------------------------
__global__ __launch_bounds__(256) void xproj_kernel(
    const float* __restrict__ x,
    const int*   __restrict__ lengths,
    const float* __restrict__ W_ih,
    const float* __restrict__ b_ih,
    const float* __restrict__ b_hh)
{
    extern __shared__ float sm[];
    float* ws = sm;                 // [256][65]
    float* xs = sm + 256 * 65;      // [64][64]

    const int b  = blockIdx.y;
    const int t0 = blockIdx.x * 64;
    const int len = lengths[b];
    if (t0 >= len) return;
    const int tcnt = min(64, len - t0);
    const int tid = threadIdx.x;

    for (int idx = tid; idx < HH * II; idx += 256) {
        int h = idx >> 6, i = idx & 63;
        ws[h * 65 + i] = W_ih[idx];
    }
    const float* xbase = x + ((size_t)b * TT + t0) * II;
    for (int idx = tid; idx < tcnt * II; idx += 256) {
        xs[idx] = xbase[idx];
    }
    __syncthreads();

    const int h = tid;
    u64 wp[II / 2];
#pragma unroll
    for (int q = 0; q < II / 2; q++)
        wp[q] = pack2(ws[h * 65 + 2 * q], ws[h * 65 + 2 * q + 1]);
    const u64 bias0 = pack2(b_ih[h] + b_hh[h], 0.f);

    float* xpb = g_xp + ((size_t)b * TT + t0) * HH + h;

    for (int tt = 0; tt < tcnt; tt++) {
        u64 acc0 = bias0, acc1 = 0ull;
        const ulonglong2* xr = (const ulonglong2*)(xs + tt * II);
#pragma unroll
        for (int q = 0; q < II / 4; q++) {
            ulonglong2 xv = xr[q];
            ffma2(acc0, wp[2 * q],     xv.x);
            ffma2(acc1, wp[2 * q + 1], xv.y);
        }
        float2 f0 = unpack2(acc0), f1 = unpack2(acc1);
        xpb[(size_t)tt * HH] = (f0.x + f0.y) + (f1.x + f1.y);
    }
}

// ---------------------------------------------------------------------------
// Kernel B: clustered persistent scan. 64 clusters x 2 CTAs x 256 threads.
// Cluster u handles batches 4u..4u+3; CTA rank r owns j in [128r, 128r+128).
// All W_hh for the CTA's j-half lives in REGISTERS (64 u64/thread).
// Warp w owns j in [128r+16w, +16); lane c handles k ≡ c (mod 32), 8 k-iters.
// h buffers (both halves, both phases): q01[k]=(h0,h1,h1,h0), q23[k]=(h2,h3,h3,h2).
// Each step: 16 LDS.128 (h) + 256 FFMA2, 5-level reduce-scatter, tanh, store
// own half locally + push to peer via st.shared::cluster, mbarrier handshake.
// ---------------------------------------------------------------------------
__global__ __launch_bounds__(256, 1) __cluster_dims__(2, 1, 1)
void scan_kernel(
    const float* __restrict__ W_hh,
    const int*   __restrict__ lengths,
    const float* __restrict__ W_fc)
{
    __shared__ float4 q01[2][HH];
    __shared__ float4 q23[2][HH];
    __shared__ float  hlast[4][128];
    __shared__ float  fcred[4][128];
    __shared__ __align__(8) u64 mbar;

    const int tid  = threadIdx.x;
    const int w    = tid >> 5;            // warp 0..7
    const int c    = tid & 31;            // lane
    const int rank = blockIdx.x & 1;      // CTA rank in cluster
    const int cl   = blockIdx.x >> 1;     // cluster id
    const int b0   = 4 * cl;

    int L0 = lengths[b0], L1 = lengths[b0+1], L2 = lengths[b0+2], L3 = lengths[b0+3];
    const int Tmax = max(max(L0, L1), max(L2, L3));
    const int jbase = 128 * rank + 16 * w;

    // All W for this thread in registers: wp[i][p] = (W[j0+2p][k], W[j0+2p+1][k]),
    // k = 32*i + c.
    u64 wp[8][8];
#pragma unroll
    for (int i = 0; i < 8; i++) {
#pragma unroll
        for (int p2 = 0; p2 < 8; p2++) {
            int k = 32 * i + c;
            int j0 = jbase + 2 * p2;
            wp[i][p2] = pack2(__ldg(&W_hh[j0 * HH + k]), __ldg(&W_hh[(j0 + 1) * HH + k]));
        }
    }

    // Zero phase-0 h buffers (read at t=0); later phases fully overwritten.
    if (tid < HH) {
        q01[0][tid] = make_float4(0.f, 0.f, 0.f, 0.f);
        q23[0][tid] = make_float4(0.f, 0.f, 0.f, 0.f);
    }
    const uint32_t bar_l = smem_u32(&mbar);
    if (tid == 0) {
        asm volatile("mbarrier.init.shared.b64 [%0], 2;" :: "r"(bar_l) : "memory");
    }
    __syncthreads();
    // Cluster-wide: peer's mbarrier + buffers ready before any remote traffic.
    asm volatile("barrier.cluster.arrive.aligned;" ::: "memory");
    asm volatile("barrier.cluster.wait.aligned;"   ::: "memory");

    const uint32_t peer = (uint32_t)(rank ^ 1);
    uint32_t rq01[2], rq23[2];
    rq01[0] = mapa_u32(smem_u32(&q01[0][0]), peer);
    rq01[1] = mapa_u32(smem_u32(&q01[1][0]), peer);
    rq23[0] = mapa_u32(smem_u32(&q23[0][0]), peer);
    rq23[1] = mapa_u32(smem_u32(&q23[1][0]), peer);
    const uint32_t bar_r = mapa_u32(bar_l, peer);

    // Per-lane final mapping after reduce-scatter: lane c gets acc[c],
    // c = 4*p + T; T: 0=(jA,b0)(jB,b1) 1=(jA,b1)(jB,b0) 2=(jA,b2)(jB,b3) 3=(jA,b3)(jB,b2)
    const int p  = c >> 2, T = c & 3;
    const int jA = jbase + 2 * p;
    const int jB = jA + 1;
    const int jl = 16 * w + 2 * p;                      // local j index
    const int ba = (T == 0) ? 0 : (T == 1) ? 1 : (T == 2) ? 2 : 3;  // batch of jA value
    const int bb = (T == 0) ? 1 : (T == 1) ? 0 : (T == 2) ? 3 : 2;  // batch of jB value
    const int La = lengths[b0 + ba];
    const int Lb = lengths[b0 + bb];
    const float* xpA = g_xp + (size_t)(b0 + ba) * TT * HH + jA;
    const float* xpB = g_xp + (size_t)(b0 + bb) * TT * HH + jB;

    float e0 = xpA[0], e1 = xpB[0];

    for (int t = 0; t < Tmax; t++) {
        const int ph = t & 1, nph = ph ^ 1;

        int tn = min(t + 1, Tmax - 1);
        float e0n = xpA[(size_t)tn * HH];
        float e1n = xpB[(size_t)tn * HH];

        u64 acc[32];
#pragma unroll
        for (int q = 0; q < 32; q++) acc[q] = 0ull;

#pragma unroll
        for (int i = 0; i < 8; i++) {
            int k = 32 * i + c;
            ulonglong2 h01 = *(const ulonglong2*)&q01[ph][k];  // .x=(h0,h1) .y=(h1,h0)
            ulonglong2 h23 = *(const ulonglong2*)&q23[ph][k];
#pragma unroll
            for (int p2 = 0; p2 < 8; p2++) {
                ffma2(acc[4 * p2 + 0], wp[i][p2], h01.x);
                ffma2(acc[4 * p2 + 1], wp[i][p2], h01.y);
                ffma2(acc[4 * p2 + 2], wp[i][p2], h23.x);
                ffma2(acc[4 * p2 + 3], wp[i][p2], h23.y);
            }
        }

        // 5-level reduce-scatter over 32 lanes; lane c ends with acc[c].
#pragma unroll
        for (int lvl = 0; lvl < 5; lvl++) {
            const int mask = 16 >> lvl;
            const int cnt  = 16 >> lvl;
            const bool hi  = (c & mask) != 0;
#pragma unroll
            for (int i2 = 0; i2 < 16; i2++) {
                if (i2 < cnt) {
                    u64 keep = hi ? acc[cnt + i2] : acc[i2];
                    u64 send = hi ? acc[i2] : acc[cnt + i2];
                    acc[i2] = add2(keep, __shfl_xor_sync(0xffffffffu, send, mask));
                }
            }
        }

        float2 f = unpack2(acc[0]);
        float v0 = tanhf(f.x + e0);        // value at (jA, ba)
        float v1 = tanhf(f.y + e1);        // value at (jB, bb)

        // Pair-exchange (xor 1) to assemble float4 (hx, hy, hy, hx) per j.
        float sendv = (c & 1) ? v0 : v1;
        float got = __shfl_xor_sync(0xffffffffu, sendv, 1);
        float4 st4; int js;
        if (!(c & 1)) { st4 = make_float4(v0, got, got, v0); js = jA; }
        else          { st4 = make_float4(v1, got, got, v1); js = jB; }

        if (T < 2) q01[nph][js] = st4; else q23[nph][js] = st4;
        uint32_t raddr = ((T < 2) ? rq01[nph] : rq23[nph]) + (uint32_t)js * 16u;
        asm volatile("st.shared::cluster.v4.f32 [%0], {%1,%2,%3,%4};"
                     :: "r"(raddr), "f"(st4.x), "f"(st4.y), "f"(st4.z), "f"(st4.w)
                     : "memory");

        if (t == La - 1) hlast[ba][jl]     = v0;
        if (t == Lb - 1) hlast[bb][jl + 1] = v1;

        e0 = e0n; e1 = e1n;

        __syncthreads();                       // all local+remote stores issued
        if (tid == 0) {
            asm volatile("fence.acq_rel.cluster;" ::: "memory");
            asm volatile("mbarrier.arrive.shared.b64 _, [%0];" :: "r"(bar_l) : "memory");
            asm volatile("mbarrier.arrive.shared::cluster.b64 _, [%0];" :: "r"(bar_r) : "memory");
        }
        {   // wait for phase t completion (2 arrives: own + peer)
            const uint32_t par = (uint32_t)(t & 1);
            uint32_t done;
            asm volatile(
                "{\n\t.reg .pred P;\n\t"
                "mbarrier.try_wait.parity.shared.b64 P, [%1], %2;\n\t"
                "selp.b32 %0, 1, 0, P;\n\t}"
                : "=r"(done) : "r"(bar_l), "r"(par) : "memory");
            while (!done) {
                asm volatile(
                    "{\n\t.reg .pred P;\n\t"
                    "mbarrier.try_wait.parity.shared.b64 P, [%1], %2;\n\t"
                    "selp.b32 %0, 1, 0, P;\n\t}"
                    : "=r"(done) : "r"(bar_l), "r"(par) : "memory");
            }
        }
        asm volatile("fence.acq_rel.cluster;" ::: "memory");  // acquire peer stores
    }

    // FC partials: g_part[b][rank] = dot(hlast[b], W_fc[128*rank ..]).
    __syncthreads();
    for (int idx = tid; idx < 4 * 128; idx += 256) {
        int bb2 = idx >> 7, jj = idx & 127;
        fcred[bb2][jj] = hlast[bb2][jj] * W_fc[128 * rank + jj];
    }
    __syncthreads();
    if (w < 4) {
        float v = fcred[w][c] + fcred[w][c + 32] + fcred[w][c + 64] + fcred[w][c + 96];
#pragma unroll
        for (int o = 16; o > 0; o >>= 1) v += __shfl_down_sync(0xffffffffu, v, o);
        if (c == 0) g_part[b0 + w][rank] = v;
    }

    // No CTA exits while peer traffic may be in flight.
    asm volatile("barrier.cluster.arrive.aligned;" ::: "memory");
    asm volatile("barrier.cluster.wait.aligned;"   ::: "memory");
}

// ---------------------------------------------------------------------------
// Kernel C: out[b] = g_part[b][0] + g_part[b][1] + b_fc
// ---------------------------------------------------------------------------
__global__ void finish_kernel(const float* __restrict__ b_fc, float* __restrict__ out)
{
    int b = threadIdx.x;
    out[b] = g_part[b][0] + g_part[b][1] + b_fc[0];
}

// ---------------------------------------------------------------------------
extern "C" void kernel_launch(void* const* d_in, const int* in_sizes, int n_in,
                              void* d_out, int out_size)
{
    const float* x     = (const float*)d_in[0];
    const int*   lens  = (const int*)  d_in[1];
    const float* W_ih  = (const float*)d_in[2];
    const float* W_hh  = (const float*)d_in[3];
    const float* b_ih  = (const float*)d_in[4];
    const float* b_hh  = (const float*)d_in[5];
    const float* W_fc  = (const float*)d_in[6];
    const float* b_fc  = (const float*)d_in[7];
    float* out = (float*)d_out;

    const int A_SMEM = (256 * 65 + 64 * 64) * 4;   // 82944 B
    cudaFuncSetAttribute(xproj_kernel, cudaFuncAttributeMaxDynamicSharedMemorySize, A_SMEM);

    dim3 gA(TT / 64, BB);
    xproj_kernel<<<gA, 256, A_SMEM>>>(x, lens, W_ih, b_ih, b_hh);
    scan_kernel<<<128, 256>>>(W_hh, lens, W_fc);
    finish_kernel<<<1, BB>>>(b_fc, out);
}

// round 7
// speedup vs baseline: 1.4771x; 1.4771x over previous
#include <cuda_runtime.h>
#include <cstdint>

#define BB 256
#define TT 2048
#define II 64
#define HH 256

// Persistent scratch for the input projection (zero-init; t>=len never written).
__device__ float g_xp[(size_t)BB * TT * HH];

typedef unsigned long long u64;

__device__ __forceinline__ u64 pack2(float lo, float hi) {
    u64 r; asm("mov.b64 %0, {%1,%2};" : "=l"(r) : "f"(lo), "f"(hi)); return r;
}
__device__ __forceinline__ void ffma2(u64& acc, u64 a, u64 b) {
    asm("fma.rn.f32x2 %0, %1, %2, %0;" : "+l"(acc) : "l"(a), "l"(b));
}
__device__ __forceinline__ u64 add2(u64 a, u64 b) {
    u64 r; asm("add.rn.f32x2 %0, %1, %2;" : "=l"(r) : "l"(a), "l"(b)); return r;
}
__device__ __forceinline__ float2 unpack2(u64 v) {
    float2 f; asm("mov.b64 {%0,%1}, %2;" : "=f"(f.x), "=f"(f.y) : "l"(v)); return f;
}

// ---------------------------------------------------------------------------
// Kernel A: xp[b,t,h] = sum_i x[b,t,i]*W_ih[h,i] + b_ih[h] + b_hh[h], t < len[b]
// ---------------------------------------------------------------------------
__global__ __launch_bounds__(256) void xproj_kernel(
    const float* __restrict__ x,
    const int*   __restrict__ lengths,
    const float* __restrict__ W_ih,
    const float* __restrict__ b_ih,
    const float* __restrict__ b_hh)
{
    extern __shared__ float sm[];
    float* ws = sm;                 // [256][65]
    float* xs = sm + 256 * 65;      // [64][64]

    const int b  = blockIdx.y;
    const int t0 = blockIdx.x * 64;
    const int len = lengths[b];
    if (t0 >= len) return;
    const int tcnt = min(64, len - t0);
    const int tid = threadIdx.x;

    for (int idx = tid; idx < HH * II; idx += 256) {
        int h = idx >> 6, i = idx & 63;
        ws[h * 65 + i] = W_ih[idx];
    }
    const float* xbase = x + ((size_t)b * TT + t0) * II;
    for (int idx = tid; idx < tcnt * II; idx += 256) {
        xs[idx] = xbase[idx];
    }
    __syncthreads();

    const int h = tid;
    u64 wp[II / 2];
#pragma unroll
    for (int q = 0; q < II / 2; q++)
        wp[q] = pack2(ws[h * 65 + 2 * q], ws[h * 65 + 2 * q + 1]);
    const u64 bias0 = pack2(b_ih[h] + b_hh[h], 0.f);

    float* xpb = g_xp + ((size_t)b * TT + t0) * HH + h;

    for (int tt = 0; tt < tcnt; tt++) {
        u64 acc0 = bias0, acc1 = 0ull;
        const ulonglong2* xr = (const ulonglong2*)(xs + tt * II);
#pragma unroll
        for (int q = 0; q < II / 4; q++) {
            ulonglong2 xv = xr[q];
            ffma2(acc0, wp[2 * q],     xv.x);
            ffma2(acc1, wp[2 * q + 1], xv.y);
        }
        float2 f0 = unpack2(acc0), f1 = unpack2(acc1);
        xpb[(size_t)tt * HH] = (f0.x + f0.y) + (f1.x + f1.y);
    }
}

// ---------------------------------------------------------------------------
// Kernel B: persistent scan, k-split 16, sigma-permuted select-free reduction.
// 128 CTAs x 256 threads, 2 batch rows/CTA.
// Thread: c = tid&15 (k ≡ c mod 16), jb = tid&240 (16-j group), σ=(c>>1)&7,
// π=c&1. Slot s ↔ actual j-pair P = s^σ (permutation folded into W load).
// X[s] = Σ (W[jP]·h_b0, W[jP+1]·h_b1) via hv=(h0,h1); Y[s] via hs=(h1,h0).
// k-iters 0..9 W in regs (80 u64); iters 10..15 W from smem rows k>=160.
// Reduce-scatter masks 8/4/2/1, all uniform adds (no selects). Lane ends with
// full X[0],Y[0] for j* = jb+2σ: outputs (j*,bπ),(j*+1,bπ). One LDG.64 xp,
// one STS.64 h, predicated STS.64 hlast.
// ---------------------------------------------------------------------------
#define RS  260
#define K0  160
#define RKI 10
#define NSM ((HH - K0) / 16)   // 6 smem k-iters

__global__ __launch_bounds__(256, 1) void scan_kernel(
    const float* __restrict__ W_hh,
    const int*   __restrict__ lengths,
    const float* __restrict__ W_fc,
    const float* __restrict__ b_fc,
    float*       __restrict__ out)
{
    extern __shared__ float sm[];
    float*  Wsm  = sm;                           // [96][260]
    float2* hb0  = (float2*)(sm + (HH - K0) * RS);   // [256]
    float2* hb1  = hb0 + HH;                     // [256]
    float*  hlast = (float*)(hb1 + HH);          // [2][256]
    float*  red   = hlast + 2 * HH;              // [16]

    const int tid = threadIdx.x;
    const int c   = tid & 15;
    const int jb  = tid & 240;
    const int sig = (c >> 1) & 7;
    const int pi  = c & 1;
    const int b0  = 2 * blockIdx.x;
    const int L0 = lengths[b0], L1 = lengths[b0 + 1];
    const int Tmax = max(L0, L1);

    // Stage W^T rows k >= K0 into smem (coalesced read of W_hh).
    for (int idx = tid; idx < HH * HH; idx += 256) {
        int j = idx >> 8, k = idx & 255;
        float v = W_hh[idx];
        if (k >= K0) Wsm[(k - K0) * RS + j] = v;
    }
    // Register W for k-iters 0..RKI-1, sigma-permuted slot assignment.
    u64 wr[RKI][8];
#pragma unroll
    for (int i = 0; i < RKI; i++) {
        int k = 16 * i + c;
#pragma unroll
        for (int s = 0; s < 8; s++) {
            int jj = jb + 2 * (s ^ sig);
            wr[i][s] = pack2(__ldg(&W_hh[jj * HH + k]),
                             __ldg(&W_hh[(jj + 1) * HH + k]));
        }
    }
    hb0[tid] = make_float2(0.f, 0.f);
    hlast[tid] = 0.f; hlast[HH + tid] = 0.f;
    __syncthreads();

    const int   Lme   = pi ? L1 : L0;
    const int   jstar = jb + 2 * sig;
    const float2* xpp = (const float2*)(g_xp + (size_t)(b0 + pi) * TT * HH + jstar);

    float2 e = xpp[0];

    for (int t = 0; t < Tmax; t++) {
        const float2* hc = (t & 1) ? hb1 : hb0;
        float2*       hn = (t & 1) ? hb0 : hb1;

        int tn = min(t + 1, Tmax - 1);
        float2 en = xpp[(size_t)tn * (HH / 2)];

        u64 X[8], Y[8];
#pragma unroll
        for (int s = 0; s < 8; s++) { X[s] = 0ull; Y[s] = 0ull; }

#pragma unroll
        for (int i = 0; i < RKI; i++) {
            float2 hvf = hc[16 * i + c];
            u64 hv = pack2(hvf.x, hvf.y);
            u64 hs = pack2(hvf.y, hvf.x);
#pragma unroll
            for (int s = 0; s < 8; s++) {
                ffma2(X[s], wr[i][s], hv);
                ffma2(Y[s], wr[i][s], hs);
            }
        }
#pragma unroll
        for (int i = RKI; i < 16; i++) {
            float2 hvf = hc[16 * i + c];
            u64 hv = pack2(hvf.x, hvf.y);
            u64 hs = pack2(hvf.y, hvf.x);
            const float* wb = Wsm + (16 * (i - RKI) + c) * RS + jb;
#pragma unroll
            for (int s = 0; s < 8; s++) {
                u64 wv = *(const u64*)(wb + 2 * (s ^ sig));   // LDS.64, 8B-aligned
                ffma2(X[s], wv, hv);
                ffma2(Y[s], wv, hs);
            }
        }

        // Select-free reduce-scatter (partner complementarity via sigma).
#pragma unroll
        for (int q = 0; q < 4; q++) {
            X[q] = add2(X[q], __shfl_xor_sync(0xffffffffu, X[q + 4], 8));
            Y[q] = add2(Y[q], __shfl_xor_sync(0xffffffffu, Y[q + 4], 8));
        }
#pragma unroll
        for (int q = 0; q < 2; q++) {
            X[q] = add2(X[q], __shfl_xor_sync(0xffffffffu, X[q + 2], 4));
            Y[q] = add2(Y[q], __shfl_xor_sync(0xffffffffu, Y[q + 2], 4));
        }
        X[0] = add2(X[0], __shfl_xor_sync(0xffffffffu, X[1], 2));
        Y[0] = add2(Y[0], __shfl_xor_sync(0xffffffffu, Y[1], 2));
        X[0] = add2(X[0], __shfl_xor_sync(0xffffffffu, X[0], 1));
        Y[0] = add2(Y[0], __shfl_xor_sync(0xffffffffu, Y[0], 1));

        float2 xf = unpack2(X[0]);   // ((j*,b0), (j*+1,b1)) fully summed
        float2 yf = unpack2(Y[0]);   // ((j*,b1), (j*+1,b0))
        float a0 = pi ? yf.x : xf.x;         // (j*,   my batch)
        float a1 = pi ? xf.y : yf.y;         // (j*+1, my batch)
        float v0 = tanhf(a0 + e.x);
        float v1 = tanhf(a1 + e.y);

        // Assemble (b0,b1) pairs with partner lane c^1 and store one float2.
        float r0 = __shfl_xor_sync(0xffffffffu, v0, 1);  // other batch @ j*
        float r1 = __shfl_xor_sync(0xffffffffu, v1, 1);  // other batch @ j*+1
        if (!pi) hn[jstar]     = make_float2(v0, r0);
        else     hn[jstar + 1] = make_float2(r1, v1);

        if (t == Lme - 1)
            *(float2*)&hlast[pi * HH + jstar] = make_float2(v0, v1);

        e = en;
        __syncthreads();   // hn visible; fences next-iter writes vs this read
    }

    // Final FC: out[b] = dot(hlast[b], W_fc) + b_fc
    float wf = W_fc[tid];
#pragma unroll
    for (int bb = 0; bb < 2; bb++) {
        float v = hlast[bb * HH + tid] * wf;
#pragma unroll
        for (int o = 16; o > 0; o >>= 1) v += __shfl_down_sync(0xffffffffu, v, o);
        if ((tid & 31) == 0) red[bb * 8 + (tid >> 5)] = v;
    }
    __syncthreads();
    if (tid < 2) {
        float s = b_fc[0];
#pragma unroll
        for (int q = 0; q < 8; q++) s += red[tid * 8 + q];
        out[b0 + tid] = s;
    }
}

// ---------------------------------------------------------------------------
extern "C" void kernel_launch(void* const* d_in, const int* in_sizes, int n_in,
                              void* d_out, int out_size)
{
    const float* x     = (const float*)d_in[0];
    const int*   lens  = (const int*)  d_in[1];
    const float* W_ih  = (const float*)d_in[2];
    const float* W_hh  = (const float*)d_in[3];
    const float* b_ih  = (const float*)d_in[4];
    const float* b_hh  = (const float*)d_in[5];
    const float* W_fc  = (const float*)d_in[6];
    const float* b_fc  = (const float*)d_in[7];
    float* out = (float*)d_out;

    const int A_SMEM = (256 * 65 + 64 * 64) * 4;                           // 82944 B
    const int B_SMEM = ((HH - K0) * RS + 2 * HH * 2 + 2 * HH + 16) * 4;    // ~106 KB
    cudaFuncSetAttribute(xproj_kernel, cudaFuncAttributeMaxDynamicSharedMemorySize, A_SMEM);
    cudaFuncSetAttribute(scan_kernel,  cudaFuncAttributeMaxDynamicSharedMemorySize, B_SMEM);

    dim3 gA(TT / 64, BB);
    xproj_kernel<<<gA, 256, A_SMEM>>>(x, lens, W_ih, b_ih, b_hh);
    scan_kernel<<<BB / 2, 256, B_SMEM>>>(W_hh, lens, W_fc, b_fc, out);
}

// round 9
// speedup vs baseline: 1.6305x; 1.1038x over previous
#include <cuda_runtime.h>
#include <cstdint>

#define BB 256
#define TT 2048
#define II 64
#define HH 256

// Persistent scratch for the input projection (zero-init; t>=len never written).
__device__ float g_xp[(size_t)BB * TT * HH];

typedef unsigned long long u64;

__device__ __forceinline__ u64 pack2(float lo, float hi) {
    u64 r; asm("mov.b64 %0, {%1,%2};" : "=l"(r) : "f"(lo), "f"(hi)); return r;
}
__device__ __forceinline__ void ffma2(u64& acc, u64 a, u64 b) {
    asm("fma.rn.f32x2 %0, %1, %2, %0;" : "+l"(acc) : "l"(a), "l"(b));
}
__device__ __forceinline__ u64 add2(u64 a, u64 b) {
    u64 r; asm("add.rn.f32x2 %0, %1, %2;" : "=l"(r) : "l"(a), "l"(b)); return r;
}
__device__ __forceinline__ float2 unpack2(u64 v) {
    float2 f; asm("mov.b64 {%0,%1}, %2;" : "=f"(f.x), "=f"(f.y) : "l"(v)); return f;
}

// ---------------------------------------------------------------------------
// Kernel A: xp[b,t,h] = sum_i x[b,t,i]*W_ih[h,i] + b_ih[h] + b_hh[h], t < len[b]
// ---------------------------------------------------------------------------
__global__ __launch_bounds__(256) void xproj_kernel(
    const float* __restrict__ x,
    const int*   __restrict__ lengths,
    const float* __restrict__ W_ih,
    const float* __restrict__ b_ih,
    const float* __restrict__ b_hh)
{
    extern __shared__ float sm[];
    float* ws = sm;                 // [256][65]
    float* xs = sm + 256 * 65;      // [64][64]

    const int b  = blockIdx.y;
    const int t0 = blockIdx.x * 64;
    const int len = lengths[b];
    if (t0 >= len) return;
    const int tcnt = min(64, len - t0);
    const int tid = threadIdx.x;

    for (int idx = tid; idx < HH * II; idx += 256) {
        int h = idx >> 6, i = idx & 63;
        ws[h * 65 + i] = W_ih[idx];
    }
    const float* xbase = x + ((size_t)b * TT + t0) * II;
    for (int idx = tid; idx < tcnt * II; idx += 256) {
        xs[idx] = xbase[idx];
    }
    __syncthreads();

    const int h = tid;
    u64 wp[II / 2];
#pragma unroll
    for (int q = 0; q < II / 2; q++)
        wp[q] = pack2(ws[h * 65 + 2 * q], ws[h * 65 + 2 * q + 1]);
    const u64 bias0 = pack2(b_ih[h] + b_hh[h], 0.f);

    float* xpb = g_xp + ((size_t)b * TT + t0) * HH + h;

    for (int tt = 0; tt < tcnt; tt++) {
        u64 acc0 = bias0, acc1 = 0ull;
        const ulonglong2* xr = (const ulonglong2*)(xs + tt * II);
#pragma unroll
        for (int q = 0; q < II / 4; q++) {
            ulonglong2 xv = xr[q];
            ffma2(acc0, wp[2 * q],     xv.x);
            ffma2(acc1, wp[2 * q + 1], xv.y);
        }
        float2 f0 = unpack2(acc0), f1 = unpack2(acc1);
        xpb[(size_t)tt * HH] = (f0.x + f0.y) + (f1.x + f1.y);
    }
}

// ---------------------------------------------------------------------------
// Kernel B: persistent scan, k-split 16, natural slot order, conflict-free
// W smem via LDS.128, select-based reduce-scatter.
// 128 CTAs x 256 threads, 2 batch rows/CTA.
// Thread: c = tid&15 (k ≡ c mod 16), jb = tid&240 (16-j group).
// Acc: X[s] += (W[jb+2s][k], W[jb+2s+1][k]) ⊙ (h0,h1); Y[s] ⊙ (h1,h0).
// k-iters 0..9: W in regs (80 u64); iters 10..15: W from smem rows k>=160,
// loaded 4x LDS.128 natural order (RS=260 ≡ 4 mod 32 words: each 8-lane
// phase tiles all 32 banks exactly -> conflict-free).
// Reduce-scatter masks 8/4/2 with keep/send selects, then X/Y merge (mask 1).
// Lane c finishes pair p=(c>>1)&7: values (jA=jb+2p, b0+pi), (jB=jA+1, b1-pi).
// FIX vs r8: pi=1 lane's h-store order is (v1, recv) = (b0@jB, b1@jB).
// ---------------------------------------------------------------------------
#define RS  260
#define K0  160
#define RKI 10
#define NSM ((HH - K0) / 16)   // 6 smem k-iters

__global__ __launch_bounds__(256, 1) void scan_kernel(
    const float* __restrict__ W_hh,
    const int*   __restrict__ lengths,
    const float* __restrict__ W_fc,
    const float* __restrict__ b_fc,
    float*       __restrict__ out)
{
    extern __shared__ float sm[];
    float*  Wsm  = sm;                               // [96][260]
    float2* hb0  = (float2*)(sm + (HH - K0) * RS);   // [256] (h_b0, h_b1)
    float2* hb1  = hb0 + HH;                         // [256]
    float*  hlast = (float*)(hb1 + HH);              // [2][256]
    float*  red   = hlast + 2 * HH;                  // [16]

    const int tid = threadIdx.x;
    const int c   = tid & 15;
    const int jb  = tid & 240;
    const int b0  = 2 * blockIdx.x;
    const int L0 = lengths[b0], L1 = lengths[b0 + 1];
    const int Tmax = max(L0, L1);

    // Stage W^T rows k >= K0 into smem (coalesced read of W_hh).
    for (int idx = tid; idx < HH * HH; idx += 256) {
        int j = idx >> 8, k = idx & 255;
        float v = W_hh[idx];
        if (k >= K0) Wsm[(k - K0) * RS + j] = v;
    }
    // Register W for k-iters 0..RKI-1, natural slot order.
    u64 wr[RKI][8];
#pragma unroll
    for (int i = 0; i < RKI; i++) {
        int k = 16 * i + c;
#pragma unroll
        for (int s = 0; s < 8; s++) {
            int jj = jb + 2 * s;
            wr[i][s] = pack2(__ldg(&W_hh[jj * HH + k]),
                             __ldg(&W_hh[(jj + 1) * HH + k]));
        }
    }
    hb0[tid] = make_float2(0.f, 0.f);
    hlast[tid] = 0.f; hlast[HH + tid] = 0.f;
    __syncthreads();

    // Final per-lane mapping.
    const int p   = (c >> 1) & 7;
    const int pi  = c & 1;
    const int jA  = jb + 2 * p;
    const int jB  = jA + 1;
    const int bA  = b0 + pi;          // batch of value at jA
    const int bBt = b0 + 1 - pi;      // batch of value at jB
    const int LA  = pi ? L1 : L0;
    const int LB  = pi ? L0 : L1;
    const float* pxA = g_xp + (size_t)bA  * TT * HH + jA;
    const float* pxB = g_xp + (size_t)bBt * TT * HH + jB;

    float eA = pxA[0], eB = pxB[0];

    for (int t = 0; t < Tmax; t++) {
        const float2* hc = (t & 1) ? hb1 : hb0;
        float2*       hn = (t & 1) ? hb0 : hb1;

        int tn = min(t + 1, Tmax - 1);
        float eAn = pxA[(size_t)tn * HH];
        float eBn = pxB[(size_t)tn * HH];

        u64 X[8], Y[8];
#pragma unroll
        for (int s = 0; s < 8; s++) { X[s] = 0ull; Y[s] = 0ull; }

#pragma unroll
        for (int i = 0; i < RKI; i++) {
            float2 hvf = hc[16 * i + c];
            u64 hv = pack2(hvf.x, hvf.y);
            u64 hs = pack2(hvf.y, hvf.x);
#pragma unroll
            for (int s = 0; s < 8; s++) {
                ffma2(X[s], wr[i][s], hv);
                ffma2(Y[s], wr[i][s], hs);
            }
        }
#pragma unroll
        for (int i = RKI; i < 16; i++) {
            float2 hvf = hc[16 * i + c];
            u64 hv = pack2(hvf.x, hvf.y);
            u64 hs = pack2(hvf.y, hvf.x);
            const float* wb = Wsm + (16 * (i - RKI) + c) * RS + jb;
#pragma unroll
            for (int q = 0; q < 4; q++) {
                ulonglong2 wv = *(const ulonglong2*)(wb + 4 * q);  // LDS.128
                ffma2(X[2 * q],     wv.x, hv);
                ffma2(X[2 * q + 1], wv.y, hv);
                ffma2(Y[2 * q],     wv.x, hs);
                ffma2(Y[2 * q + 1], wv.y, hs);
            }
        }

        // Reduce-scatter with keep/send selects: masks 8, 4, 2 on slots.
        const bool h3 = (c & 8) != 0;
#pragma unroll
        for (int q = 0; q < 4; q++) {
            u64 kx = h3 ? X[q + 4] : X[q];
            u64 sx = h3 ? X[q] : X[q + 4];
            X[q] = add2(kx, __shfl_xor_sync(0xffffffffu, sx, 8));
            u64 ky = h3 ? Y[q + 4] : Y[q];
            u64 sy = h3 ? Y[q] : Y[q + 4];
            Y[q] = add2(ky, __shfl_xor_sync(0xffffffffu, sy, 8));
        }
        const bool h2 = (c & 4) != 0;
#pragma unroll
        for (int q = 0; q < 2; q++) {
            u64 kx = h2 ? X[q + 2] : X[q];
            u64 sx = h2 ? X[q] : X[q + 2];
            X[q] = add2(kx, __shfl_xor_sync(0xffffffffu, sx, 4));
            u64 ky = h2 ? Y[q + 2] : Y[q];
            u64 sy = h2 ? Y[q] : Y[q + 2];
            Y[q] = add2(ky, __shfl_xor_sync(0xffffffffu, sy, 4));
        }
        const bool h1 = (c & 2) != 0;
        {
            u64 kx = h1 ? X[1] : X[0];
            u64 sx = h1 ? X[0] : X[1];
            X[0] = add2(kx, __shfl_xor_sync(0xffffffffu, sx, 2));
            u64 ky = h1 ? Y[1] : Y[0];
            u64 sy = h1 ? Y[0] : Y[1];
            Y[0] = add2(ky, __shfl_xor_sync(0xffffffffu, sy, 2));
        }
        // Mask 1: merge X/Y by parity.
        u64 kf = pi ? Y[0] : X[0];
        u64 sf = pi ? X[0] : Y[0];
        u64 F  = add2(kf, __shfl_xor_sync(0xffffffffu, sf, 1));

        float2 f = unpack2(F);
        float v0 = tanhf(f.x + eA);      // (jA, bA)
        float v1 = tanhf(f.y + eB);      // (jB, bBt)

        // Exchange with parity partner so each lane stores one float2 (b0,b1).
        // pi=0 lane: owns b0@jA, receives b1@jA  -> hn[jA] = (v0, recv)
        // pi=1 lane: owns b0@jB, receives b1@jB  -> hn[jB] = (v1, recv)
        float sendv = pi ? v0 : v1;
        float recv  = __shfl_xor_sync(0xffffffffu, sendv, 1);
        if (!pi) hn[jA] = make_float2(v0, recv);
        else     hn[jB] = make_float2(v1, recv);

        if (t == LA - 1) hlast[pi * HH + jA]       = v0;
        if (t == LB - 1) hlast[(1 - pi) * HH + jB] = v1;

        eA = eAn; eB = eBn;
        __syncthreads();   // hn visible; fences next-iter writes vs reads
    }

    // Final FC: out[b] = dot(hlast[b], W_fc) + b_fc
    float wf = W_fc[tid];
#pragma unroll
    for (int bb = 0; bb < 2; bb++) {
        float v = hlast[bb * HH + tid] * wf;
#pragma unroll
        for (int o = 16; o > 0; o >>= 1) v += __shfl_down_sync(0xffffffffu, v, o);
        if ((tid & 31) == 0) red[bb * 8 + (tid >> 5)] = v;
    }
    __syncthreads();
    if (tid < 2) {
        float s = b_fc[0];
#pragma unroll
        for (int q = 0; q < 8; q++) s += red[tid * 8 + q];
        out[b0 + tid] = s;
    }
}

// ---------------------------------------------------------------------------
extern "C" void kernel_launch(void* const* d_in, const int* in_sizes, int n_in,
                              void* d_out, int out_size)
{
    const float* x     = (const float*)d_in[0];
    const int*   lens  = (const int*)  d_in[1];
    const float* W_ih  = (const float*)d_in[2];
    const float* W_hh  = (const float*)d_in[3];
    const float* b_ih  = (const float*)d_in[4];
    const float* b_hh  = (const float*)d_in[5];
    const float* W_fc  = (const float*)d_in[6];
    const float* b_fc  = (const float*)d_in[7];
    float* out = (float*)d_out;

    const int A_SMEM = (256 * 65 + 64 * 64) * 4;                           // 82944 B
    const int B_SMEM = ((HH - K0) * RS + 2 * HH * 2 + 2 * HH + 16) * 4;    // ~106 KB
    cudaFuncSetAttribute(xproj_kernel, cudaFuncAttributeMaxDynamicSharedMemorySize, A_SMEM);
    cudaFuncSetAttribute(scan_kernel,  cudaFuncAttributeMaxDynamicSharedMemorySize, B_SMEM);

    dim3 gA(TT / 64, BB);
    xproj_kernel<<<gA, 256, A_SMEM>>>(x, lens, W_ih, b_ih, b_hh);
    scan_kernel<<<BB / 2, 256, B_SMEM>>>(W_hh, lens, W_fc, b_fc, out);
}

// round 10
// speedup vs baseline: 1.7369x; 1.0653x over previous
#include <cuda_runtime.h>
#include <cstdint>

#define BB 256
#define TT 2048
#define II 64
#define HH 256

// Persistent scratch for the input projection (zero-init; t>=len never written).
__device__ float g_xp[(size_t)BB * TT * HH];

typedef unsigned long long u64;

__device__ __forceinline__ u64 pack2(float lo, float hi) {
    u64 r; asm("mov.b64 %0, {%1,%2};" : "=l"(r) : "f"(lo), "f"(hi)); return r;
}
__device__ __forceinline__ u64 dup2(float v) {
    u64 r; asm("mov.b64 %0, {%1,%1};" : "=l"(r) : "f"(v)); return r;
}
__device__ __forceinline__ void ffma2(u64& acc, u64 a, u64 b) {
    asm("fma.rn.f32x2 %0, %1, %2, %0;" : "+l"(acc) : "l"(a), "l"(b));
}
__device__ __forceinline__ u64 add2(u64 a, u64 b) {
    u64 r; asm("add.rn.f32x2 %0, %1, %2;" : "=l"(r) : "l"(a), "l"(b)); return r;
}
__device__ __forceinline__ float2 unpack2(u64 v) {
    float2 f; asm("mov.b64 {%0,%1}, %2;" : "=f"(f.x), "=f"(f.y) : "l"(v)); return f;
}
__device__ __forceinline__ float tanhap(float x) {
    float y; asm("tanh.approx.f32 %0, %1;" : "=f"(y) : "f"(x)); return y;
}
__device__ __forceinline__ u64 shfl64(u64 v, int mask) {
    return __shfl_xor_sync(0xffffffffu, v, mask);
}

// ---------------------------------------------------------------------------
// Kernel A: xp[b,t,h] = sum_i x[b,t,i]*W_ih[h,i] + b_ih[h] + b_hh[h], t < len[b]
// ---------------------------------------------------------------------------
__global__ __launch_bounds__(256) void xproj_kernel(
    const float* __restrict__ x,
    const int*   __restrict__ lengths,
    const float* __restrict__ W_ih,
    const float* __restrict__ b_ih,
    const float* __restrict__ b_hh)
{
    extern __shared__ float sm[];
    float* ws = sm;                 // [256][65]
    float* xs = sm + 256 * 65;      // [64][64]

    const int b  = blockIdx.y;
    const int t0 = blockIdx.x * 64;
    const int len = lengths[b];
    if (t0 >= len) return;
    const int tcnt = min(64, len - t0);
    const int tid = threadIdx.x;

    for (int idx = tid; idx < HH * II; idx += 256) {
        int h = idx >> 6, i = idx & 63;
        ws[h * 65 + i] = W_ih[idx];
    }
    const float* xbase = x + ((size_t)b * TT + t0) * II;
    for (int idx = tid; idx < tcnt * II; idx += 256) {
        xs[idx] = xbase[idx];
    }
    __syncthreads();

    const int h = tid;
    u64 wp[II / 2];
#pragma unroll
    for (int q = 0; q < II / 2; q++)
        wp[q] = pack2(ws[h * 65 + 2 * q], ws[h * 65 + 2 * q + 1]);
    const u64 bias0 = pack2(b_ih[h] + b_hh[h], 0.f);

    float* xpb = g_xp + ((size_t)b * TT + t0) * HH + h;

    for (int tt = 0; tt < tcnt; tt++) {
        u64 acc0 = bias0, acc1 = 0ull;
        const ulonglong2* xr = (const ulonglong2*)(xs + tt * II);
#pragma unroll
        for (int q = 0; q < II / 4; q++) {
            ulonglong2 xv = xr[q];
            ffma2(acc0, wp[2 * q],     xv.x);
            ffma2(acc1, wp[2 * q + 1], xv.y);
        }
        float2 f0 = unpack2(acc0), f1 = unpack2(acc1);
        xpb[(size_t)tt * HH] = (f0.x + f0.y) + (f1.x + f1.y);
    }
}

// ---------------------------------------------------------------------------
// Kernel B: persistent scan = round-2 inner loop (best measured) + short tail.
// 128 CTAs x 256 threads, 2 batch rows/CTA.
// Thread (g=tid>>2, c=tid&3): owns j-quad [4g,4g+4), k ≡ c (mod 4).
// W^T rows k<KSM in smem fp32 (stride RS=264 -> conflict-free LDS.128);
// rows k>=KSM packed in registers as f32x2 pairs. h as float2 (h_b0,h_b1).
// Tail: 2-level u64 reduce-scatter (3 shfl64) -> lane c holds full sums for
// j-pair jp=4g+2(c&1), batch b0+(c>>1); tanh.approx; shfl64 batch-exchange;
// even lanes store one STS.128 into hnxt.
// ---------------------------------------------------------------------------
#define RS 264
#define KSM 80
#define SMI (KSM / 4)            // 20 smem k-iterations
#define RGI ((HH - KSM) / 4)     // 44 register k-iterations

__global__ __launch_bounds__(256, 1) void scan_kernel(
    const float* __restrict__ W_hh,
    const int*   __restrict__ lengths,
    const float* __restrict__ W_fc,
    const float* __restrict__ b_fc,
    float*       __restrict__ out)
{
    extern __shared__ float sm[];
    float*  WT_s = sm;                          // [KSM][RS]
    float2* hb0  = (float2*)(sm + KSM * RS);    // [256] (h_b0, h_b1)
    float2* hb1  = hb0 + HH;                    // [256]
    float*  hlast = (float*)(hb1 + HH);         // [2][256]
    float*  red   = hlast + 2 * HH;             // [16]

    const int tid = threadIdx.x;
    const int c = tid & 3;
    const int g = tid >> 2;
    const int b0 = blockIdx.x * 2, b1 = b0 + 1;
    const int L0 = lengths[b0], L1 = lengths[b1];
    const int Tmax = max(L0, L1);

    // Stage W^T rows k < KSM into smem (coalesced read of W_hh).
    for (int idx = tid; idx < HH * HH; idx += 256) {
        int j = idx >> 8, k = idx & 255;
        float v = W_hh[idx];
        if (k < KSM) WT_s[k * RS + j] = v;
    }
    // Register-resident packed W pairs for k in [KSM, 256).
    u64 wpA[RGI], wpB[RGI];
#pragma unroll
    for (int ii = 0; ii < RGI; ii++) {
        int k = KSM + 4 * ii + c;
        wpA[ii] = pack2(__ldg(&W_hh[(4 * g + 0) * HH + k]),
                        __ldg(&W_hh[(4 * g + 1) * HH + k]));
        wpB[ii] = pack2(__ldg(&W_hh[(4 * g + 2) * HH + k]),
                        __ldg(&W_hh[(4 * g + 3) * HH + k]));
    }
    hb0[tid] = make_float2(0.f, 0.f);
    hlast[tid] = 0.f; hlast[HH + tid] = 0.f;
    __syncthreads();

    // Per-lane tail mapping: batch bsel = b0 + (c>>1), j-pair jp = 4g + 2*(c&1).
    const int  bsh  = c >> 1;
    const int  jp   = 4 * g + 2 * (c & 1);
    const int  Lsel = bsh ? L1 : L0;
    const float2* px = (const float2*)(g_xp + (size_t)(b0 + bsh) * TT * HH + jp);

    const unsigned base_s = c * RS + 4 * g;
    float2 xq = px[0];                      // xp for t = 0

    for (int t = 0; t < Tmax; t++) {
        const float2* hcur = (t & 1) ? hb1 : hb0;
        float2*       hnxt = (t & 1) ? hb0 : hb1;

        // prefetch xp for t+1 (consumed next iteration)
        int tn = min(t + 1, Tmax - 1);
        float2 xq_next = px[(size_t)tn * (HH / 2)];

        u64 aA = 0ull, aB = 0ull;   // batch b0: (j0,j1),(j2,j3)
        u64 cA = 0ull, cB = 0ull;   // batch b1

#pragma unroll
        for (int i = 0; i < SMI; i++) {
            ulonglong2 wv = *(const ulonglong2*)&WT_s[base_s + (unsigned)(4 * i) * RS];
            float2 hv = hcur[4 * i + c];
            u64 d0 = dup2(hv.x), d1 = dup2(hv.y);
            ffma2(aA, wv.x, d0); ffma2(aB, wv.y, d0);
            ffma2(cA, wv.x, d1); ffma2(cB, wv.y, d1);
        }
#pragma unroll
        for (int ii = 0; ii < RGI; ii++) {
            float2 hv = hcur[KSM + 4 * ii + c];
            u64 d0 = dup2(hv.x), d1 = dup2(hv.y);
            ffma2(aA, wpA[ii], d0); ffma2(aB, wpB[ii], d0);
            ffma2(cA, wpA[ii], d1); ffma2(cB, wpB[ii], d1);
        }

        // 2-level u64 reduce-scatter over the 4 k-split lanes.
        // Level mask 2 (batch split): lane keeps its final batch's items.
        const bool hi2 = (c & 2) != 0;
        u64 keepA = hi2 ? cA : aA,  sendA = hi2 ? aA : cA;
        u64 keepB = hi2 ? cB : aB,  sendB = hi2 ? aB : cB;
        u64 PA = add2(keepA, shfl64(sendA, 2));
        u64 PB = add2(keepB, shfl64(sendB, 2));
        // Level mask 1 (j-pair split).
        const bool hi1 = (c & 1) != 0;
        u64 keepF = hi1 ? PB : PA,  sendF = hi1 ? PA : PB;
        u64 F = add2(keepF, shfl64(sendF, 1));

        float2 f = unpack2(F);
        float v0 = tanhap(f.x + xq.x);      // h_{bsel}[jp]
        float v1 = tanhap(f.y + xq.y);      // h_{bsel}[jp+1]

        // Exchange with batch-partner (lane c^2) and have even-batch lanes
        // store both batches' values for (jp, jp+1) as one STS.128.
        u64 V = pack2(v0, v1);
        u64 R = shfl64(V, 2);               // other batch, same j-pair
        if (!hi2) {
            float2 r = unpack2(R);
            *(float4*)&hnxt[jp] = make_float4(v0, r.x, v1, r.y);
        }

        if (t == Lsel - 1)
            *(float2*)&hlast[bsh * HH + jp] = make_float2(v0, v1);

        xq = xq_next;
        __syncthreads();   // hnxt visible; fences next-iter writes vs reads
    }

    // Final FC: out[b] = dot(hlast[b], W_fc) + b_fc
    float wf = W_fc[tid];
#pragma unroll
    for (int bb = 0; bb < 2; bb++) {
        float v = hlast[bb * HH + tid] * wf;
#pragma unroll
        for (int o = 16; o > 0; o >>= 1) v += __shfl_down_sync(0xffffffffu, v, o);
        if ((tid & 31) == 0) red[bb * 8 + (tid >> 5)] = v;
    }
    __syncthreads();
    if (tid < 2) {
        float s = b_fc[0];
#pragma unroll
        for (int q = 0; q < 8; q++) s += red[tid * 8 + q];
        out[b0 + tid] = s;
    }
}

// ---------------------------------------------------------------------------
extern "C" void kernel_launch(void* const* d_in, const int* in_sizes, int n_in,
                              void* d_out, int out_size)
{
    const float* x     = (const float*)d_in[0];
    const int*   lens  = (const int*)  d_in[1];
    const float* W_ih  = (const float*)d_in[2];
    const float* W_hh  = (const float*)d_in[3];
    const float* b_ih  = (const float*)d_in[4];
    const float* b_hh  = (const float*)d_in[5];
    const float* W_fc  = (const float*)d_in[6];
    const float* b_fc  = (const float*)d_in[7];
    float* out = (float*)d_out;

    const int A_SMEM = (256 * 65 + 64 * 64) * 4;                        // 82944 B
    const int B_SMEM = (KSM * RS + 2 * HH * 2 + 2 * HH + 16) * 4;       // ~91 KB
    cudaFuncSetAttribute(xproj_kernel, cudaFuncAttributeMaxDynamicSharedMemorySize, A_SMEM);
    cudaFuncSetAttribute(scan_kernel,  cudaFuncAttributeMaxDynamicSharedMemorySize, B_SMEM);

    dim3 gA(TT / 64, BB);
    xproj_kernel<<<gA, 256, A_SMEM>>>(x, lens, W_ih, b_ih, b_hh);
    scan_kernel<<<BB / 2, 256, B_SMEM>>>(W_hh, lens, W_fc, b_fc, out);
}